// round 6
// baseline (speedup 1.0000x reference)
#include <cuda_runtime.h>
#include <cstdint>

#define Sn 512
#define Bn 64
#define Hd 1024
#define Ln 5

// scratch: emissions padded to stride 8; per-batch loss terms; block counter
__device__ float g_emis[(size_t)Bn * Sn * 8];
__device__ float g_diff[Bn];
__device__ unsigned int g_cnt;

// ---------------------------------------------------------------------------
// Kernel 1 v4: emissions = relu(feats @ W + b)  via cp.async smem pipeline.
// CTA = 32 rows, 4 stages of 8 rows (32KB), double-buffered cp.async ->
// 2 CTAs/SM x 2 stages x 32KB = 128KB continuously in flight per SM.
// Compute: warp-per-row from smem (conflict-free LDS.128), W^T in smem.
// ---------------------------------------------------------------------------
__device__ __forceinline__ void issue_stage(const float* gsrc_t, float* dbase_t, int s) {
    const float* src = gsrc_t + s * 8192;
    float* dst = dbase_t + (s & 1) * 8192;
#pragma unroll
    for (int kk = 0; kk < 8; kk++) {
        unsigned int d = (unsigned int)__cvta_generic_to_shared(dst + kk * 1024);
        asm volatile("cp.async.cg.shared.global [%0], [%1], 16;"
                     :: "r"(d), "l"(src + kk * 1024));
    }
    asm volatile("cp.async.commit_group;" ::: "memory");
}

__global__ __launch_bounds__(256, 2) void k_emis(const float* __restrict__ feats,
                                                 const float* __restrict__ W,
                                                 const float* __restrict__ bias) {
    extern __shared__ float sm[];
    float* sWT = sm;                 // [5][1024] transposed weights (20KB)
    float* sBuf = sm + Ln * Hd;      // 2 x 8192 floats (64KB)

    const int tid = threadIdx.x;
    for (int i = tid; i < Ln * Hd; i += 256) {
        int j = i >> 10;
        int k = i & (Hd - 1);
        sWT[i] = W[k * Ln + j];
    }

    const float* gsrc = feats + (size_t)blockIdx.x * 32 * Hd + tid * 4;
    float* dbase = sBuf + tid * 4;

    issue_stage(gsrc, dbase, 0);
    issue_stage(gsrc, dbase, 1);

    const int warp = tid >> 5, lane = tid & 31;

#pragma unroll
    for (int s = 0; s < 4; s++) {
        if (s < 3) asm volatile("cp.async.wait_group 1;" ::: "memory");
        else       asm volatile("cp.async.wait_group 0;" ::: "memory");
        __syncthreads();  // stage data + (s==0) sWT visible to all

        const float* rA = sBuf + (s & 1) * 8192 + warp * Hd;
        float a0 = 0.f, a1 = 0.f, a2 = 0.f, a3 = 0.f, a4 = 0.f;
#pragma unroll
        for (int c = 0; c < 8; c++) {
            int k = c * 128 + lane * 4;
            float4 f  = *reinterpret_cast<const float4*>(rA + k);
            float4 w0 = *reinterpret_cast<const float4*>(sWT + k);
            float4 w1 = *reinterpret_cast<const float4*>(sWT + Hd + k);
            float4 w2 = *reinterpret_cast<const float4*>(sWT + 2 * Hd + k);
            float4 w3 = *reinterpret_cast<const float4*>(sWT + 3 * Hd + k);
            float4 w4 = *reinterpret_cast<const float4*>(sWT + 4 * Hd + k);
            a0 = fmaf(f.x, w0.x, fmaf(f.y, w0.y, fmaf(f.z, w0.z, fmaf(f.w, w0.w, a0))));
            a1 = fmaf(f.x, w1.x, fmaf(f.y, w1.y, fmaf(f.z, w1.z, fmaf(f.w, w1.w, a1))));
            a2 = fmaf(f.x, w2.x, fmaf(f.y, w2.y, fmaf(f.z, w2.z, fmaf(f.w, w2.w, a2))));
            a3 = fmaf(f.x, w3.x, fmaf(f.y, w3.y, fmaf(f.z, w3.z, fmaf(f.w, w3.w, a3))));
            a4 = fmaf(f.x, w4.x, fmaf(f.y, w4.y, fmaf(f.z, w4.z, fmaf(f.w, w4.w, a4))));
        }
#pragma unroll
        for (int o = 16; o; o >>= 1) {
            a0 += __shfl_xor_sync(0xffffffffu, a0, o);
            a1 += __shfl_xor_sync(0xffffffffu, a1, o);
            a2 += __shfl_xor_sync(0xffffffffu, a2, o);
            a3 += __shfl_xor_sync(0xffffffffu, a3, o);
            a4 += __shfl_xor_sync(0xffffffffu, a4, o);
        }
        if (lane < 5) {
            float v = (lane == 0) ? a0 : (lane == 1) ? a1 : (lane == 2) ? a2
                    : (lane == 3) ? a3 : a4;
            int row_g = blockIdx.x * 32 + s * 8 + warp;
            g_emis[(size_t)row_g * 8 + lane] = fmaxf(v + bias[lane], 0.0f);
        }
        __syncthreads();  // all warps done reading buf (s&1) before refill
        if (s < 2) issue_stage(gsrc, dbase, s + 2);
    }
}

// ---------------------------------------------------------------------------
// Kernel 2: one block (512 thr) per batch.
//   warp 0      : sequential Viterbi (bit-exact), stores bp bytes
//   warp 1      : numerator, then (bar 1) forward serial combine
//   warps 8-15  : forward partition fn as 8 chunked 5x5 prob-domain matrix
//                 products, hidden under Viterbi
//   all 16 warps: chunked-exact parallel backtrack
//   last block  : reduces g_diff -> out[0] (k_final merged in)
// ---------------------------------------------------------------------------
__global__ __launch_bounds__(512) void k_scan(const int* __restrict__ labels,
                                              const float* __restrict__ start_t,
                                              const float* __restrict__ end_t,
                                              const float* __restrict__ trans,
                                              const float* __restrict__ weights,
                                              float* __restrict__ out) {
    __shared__ float sh_e[Sn * 8];            // 16 KB emissions
    __shared__ float sh_x[Sn * 8];            // 16 KB exp(emissions)
    __shared__ unsigned char sh_bp[Sn * 8];   // 4 KB Viterbi backpointers
    __shared__ unsigned char sh_cand[16 * 5 * 32];
    __shared__ unsigned char sh_map[16 * 8];
    __shared__ int sh_exit[16];
    __shared__ float sh_fwdM[8][25];
    __shared__ float sh_fwdS[8];
    __shared__ float sh_num, sh_logz;
    __shared__ int sh_last;
    __shared__ int sh_is_last_blk;

    const int b = blockIdx.x;
    const int tid = threadIdx.x;
    const int warp = tid >> 5;
    const int lane = tid & 31;

    // ---- stage emissions + exp(emissions) into shared ----
    {
        const float4* src = reinterpret_cast<const float4*>(g_emis + (size_t)b * Sn * 8);
        float4* de = reinterpret_cast<float4*>(sh_e);
        float4* dx = reinterpret_cast<float4*>(sh_x);
        for (int i = tid; i < Sn * 2; i += 512) {
            float4 v = src[i];
            de[i] = v;
            float4 xv;
            xv.x = __expf(v.x); xv.y = __expf(v.y);
            xv.z = __expf(v.z); xv.w = __expf(v.w);
            dx[i] = xv;
        }
    }
    __syncthreads();

    if (warp == 0) {
        // ================= sequential Viterbi (exact) =================
        const int jj = (lane < 5) ? lane : 0;
        const float T0 = trans[0 * Ln + jj];
        const float T1 = trans[1 * Ln + jj];
        const float T2 = trans[2 * Ln + jj];
        const float T3 = trans[3 * Ln + jj];
        const float T4 = trans[4 * Ln + jj];

        float v = start_t[jj] + sh_e[0 * 8 + jj];

        for (int t = 1; t < Sn; t++) {
            float e = sh_e[t * 8 + jj];

            float a0 = __shfl_sync(0xffffffffu, v, 0);
            float a1 = __shfl_sync(0xffffffffu, v, 1);
            float a2 = __shfl_sync(0xffffffffu, v, 2);
            float a3 = __shfl_sync(0xffffffffu, v, 3);
            float a4 = __shfl_sync(0xffffffffu, v, 4);

            float s0 = a0 + T0, s1 = a1 + T1, s2 = a2 + T2, s3 = a3 + T3, s4 = a4 + T4;
            float m01 = fmaxf(s0, s1), m23 = fmaxf(s2, s3);
            float best = fmaxf(fmaxf(m01, m23), s4);
            int bi = (best == s0) ? 0 : (best == s1) ? 1 : (best == s2) ? 2
                   : (best == s3) ? 3 : 4;
            if (lane < 5) sh_bp[t * 8 + lane] = (unsigned char)bi;
            v = best + e;
        }

        float score = v + end_t[jj];
        float s0 = __shfl_sync(0xffffffffu, score, 0);
        float s1 = __shfl_sync(0xffffffffu, score, 1);
        float s2 = __shfl_sync(0xffffffffu, score, 2);
        float s3 = __shfl_sync(0xffffffffu, score, 3);
        float s4 = __shfl_sync(0xffffffffu, score, 4);
        if (lane == 0) {
            float best = fmaxf(fmaxf(fmaxf(s0, s1), fmaxf(s2, s3)), s4);
            sh_last = (best == s0) ? 0 : (best == s1) ? 1 : (best == s2) ? 2
                    : (best == s3) ? 3 : 4;
        }
    } else if (warp == 1) {
        // ================= numerator =================
        const int* lab = labels + b * Sn;
        float acc = 0.0f;
        for (int t = lane; t < Sn; t += 32) {
            int l = lab[t];
            acc = fmaf(weights[l], sh_e[t * 8 + l], acc);
            if (t > 0) acc += trans[lab[t - 1] * Ln + l];
        }
#pragma unroll
        for (int o = 16; o; o >>= 1) acc += __shfl_xor_sync(0xffffffffu, acc, o);
        if (lane == 0) {
            acc += start_t[lab[0]] + end_t[lab[Sn - 1]];
            sh_num = acc;
        }
        asm volatile("bar.sync 1, 288;" ::: "memory");
        // ---- serial combine of 8 chunk matrices -> logZ ----
        if (lane == 0) {
            float a0 = __expf(start_t[0] + sh_e[0]);
            float a1 = __expf(start_t[1] + sh_e[1]);
            float a2 = __expf(start_t[2] + sh_e[2]);
            float a3 = __expf(start_t[3] + sh_e[3]);
            float a4 = __expf(start_t[4] + sh_e[4]);
            float ls = 0.0f;
#pragma unroll
            for (int c = 0; c < 8; c++) {
                const float* M = sh_fwdM[c];
                float n0 = a0*M[0] + a1*M[5] + a2*M[10] + a3*M[15] + a4*M[20];
                float n1 = a0*M[1] + a1*M[6] + a2*M[11] + a3*M[16] + a4*M[21];
                float n2 = a0*M[2] + a1*M[7] + a2*M[12] + a3*M[17] + a4*M[22];
                float n3 = a0*M[3] + a1*M[8] + a2*M[13] + a3*M[18] + a4*M[23];
                float n4 = a0*M[4] + a1*M[9] + a2*M[14] + a3*M[19] + a4*M[24];
                float m = fmaxf(fmaxf(fmaxf(n0, n1), fmaxf(n2, n3)), n4);
                float inv = __fdividef(1.0f, m);
                a0 = n0 * inv; a1 = n1 * inv; a2 = n2 * inv; a3 = n3 * inv; a4 = n4 * inv;
                ls += __logf(m) + sh_fwdS[c];
            }
            float z = a0 * __expf(end_t[0]) + a1 * __expf(end_t[1])
                    + a2 * __expf(end_t[2]) + a3 * __expf(end_t[3])
                    + a4 * __expf(end_t[4]);
            sh_logz = __logf(z) + ls;
        }
    } else if (warp >= 8) {
        // ================= forward: chunked 5x5 matrix products =================
        const int fc = warp - 8;
        const int i = (lane < 25) ? (lane / 5) : 0;
        const int j = lane % 5;
        float eT0 = __expf(trans[0 * Ln + j]);
        float eT1 = __expf(trans[1 * Ln + j]);
        float eT2 = __expf(trans[2 * Ln + j]);
        float eT3 = __expf(trans[3 * Ln + j]);
        float eT4 = __expf(trans[4 * Ln + j]);

        float m = (i == j) ? 1.0f : 0.0f;
        float lsc = 0.0f;
        const int t0 = (fc == 0) ? 1 : 64 * fc;
        const int t1 = 64 * fc + 63;
        int cnt = 0;
        const int base = i * 5;
        for (int t = t0; t <= t1; t++) {
            float x = sh_x[t * 8 + j];
            float r0 = __shfl_sync(0xffffffffu, m, base + 0);
            float r1 = __shfl_sync(0xffffffffu, m, base + 1);
            float r2 = __shfl_sync(0xffffffffu, m, base + 2);
            float r3 = __shfl_sync(0xffffffffu, m, base + 3);
            float r4 = __shfl_sync(0xffffffffu, m, base + 4);
            float s = r0 * eT0;
            s = fmaf(r1, eT1, s);
            s = fmaf(r2, eT2, s);
            s = fmaf(r3, eT3, s);
            s = fmaf(r4, eT4, s);
            m = s * x;
            if ((++cnt & 7) == 0) {
                float mm = (lane < 25) ? m : 0.0f;
#pragma unroll
                for (int o = 16; o; o >>= 1)
                    mm = fmaxf(mm, __shfl_xor_sync(0xffffffffu, mm, o));
                m = __fdividef(m, mm);
                lsc += __logf(mm);
            }
        }
        if (lane < 25) sh_fwdM[fc][lane] = m;
        if (lane == 0) sh_fwdS[fc] = lsc;
        asm volatile("bar.sync 1, 288;" ::: "memory");
    }

    __syncthreads();  // bp + sh_last + sh_num + sh_logz ready

    if (tid == 0) {
        g_diff[b] = sh_num - sh_logz;
        __threadfence();
        unsigned int old = atomicAdd(&g_cnt, 1u);
        sh_is_last_blk = (old == Bn - 1);
    }

    // ================= chunked-exact parallel backtrack =================
    {
        const int c = warp;
        if (lane < 5) {
            int tag = lane;
            const int tstart = (c == 0) ? 1 : 32 * c;
            for (int t = 32 * c + 31; t >= tstart; t--) {
                sh_cand[(c * 5 + lane) * 32 + (t - 32 * c)] = (unsigned char)tag;
                tag = sh_bp[t * 8 + tag];
            }
            if (c == 0) sh_cand[lane * 32 + 0] = (unsigned char)tag;
            sh_map[c * 8 + lane] = (unsigned char)tag;
        }
    }
    __syncthreads();

    if (tid == 0) {
        int tg = sh_last;
        sh_exit[15] = tg;
        for (int c = 15; c >= 1; c--) {
            tg = sh_map[c * 8 + tg];
            sh_exit[c - 1] = tg;
        }
    }
    __syncthreads();

    {
        const int c = warp;
        const int ex = sh_exit[c];
        out[1 + (size_t)b * Sn + c * 32 + lane] =
            (float)sh_cand[(c * 5 + ex) * 32 + lane];
    }

    __syncthreads();
    // ---- merged k_final: last block to finish reduces g_diff -> loss ----
    if (sh_is_last_blk && warp == 0) {
        __threadfence();
        float acc = __ldcg(&g_diff[lane]) + __ldcg(&g_diff[lane + 32]);
#pragma unroll
        for (int o = 16; o; o >>= 1) acc += __shfl_xor_sync(0xffffffffu, acc, o);
        if (lane == 0) {
            out[0] = -acc * (1.0f / (float)(Bn * Sn));
            g_cnt = 0;  // reset for next graph replay
        }
    }
}

extern "C" void kernel_launch(void* const* d_in, const int* in_sizes, int n_in,
                              void* d_out, int out_size) {
    const float* feats   = (const float*)d_in[0];
    const int*   labels  = (const int*)  d_in[1];
    // d_in[2] = mask (all ones; reference requires mask[:,0] on)
    const float* W       = (const float*)d_in[3];
    const float* bias    = (const float*)d_in[4];
    const float* start_t = (const float*)d_in[5];
    const float* end_t   = (const float*)d_in[6];
    const float* trans   = (const float*)d_in[7];
    const float* weights = (const float*)d_in[8];
    float* out = (float*)d_out;

    const int smem_bytes = (Ln * Hd + 2 * 8192) * sizeof(float);  // 86016
    cudaFuncSetAttribute(k_emis, cudaFuncAttributeMaxDynamicSharedMemorySize, smem_bytes);
    k_emis<<<1024, 256, smem_bytes>>>(feats, W, bias);
    k_scan<<<Bn, 512>>>(labels, start_t, end_t, trans, weights, out);
}

// round 7
// speedup vs baseline: 1.4029x; 1.4029x over previous
#include <cuda_runtime.h>
#include <cstdint>

#define Sn 512
#define Bn 64
#define Hd 1024
#define Ln 5

// scratch: emissions padded to stride 8; per-batch loss terms; block counter
__device__ float g_emis[(size_t)Bn * Sn * 8];
__device__ float g_diff[Bn];
__device__ unsigned int g_cnt;

// ---------------------------------------------------------------------------
// Kernel 1 (R5 version, measured 36.4us): emissions = relu(feats @ W + b)
// double-buffered register prefetch, 2 blocks/SM, warp owns 4 rows.
// ---------------------------------------------------------------------------
__global__ __launch_bounds__(256, 2) void k_emis(const float* __restrict__ feats,
                                                 const float* __restrict__ W,
                                                 const float* __restrict__ bias) {
    __shared__ float sWT[Ln * Hd];  // transposed: sWT[j*Hd + k] = W[k*Ln + j]
    int tid = threadIdx.x;
    for (int i = tid; i < Ln * Hd; i += 256) {
        int j = i >> 10;
        int k = i & (Hd - 1);
        sWT[i] = W[k * Ln + j];
    }
    __syncthreads();

    int warp = tid >> 5, lane = tid & 31;
    int row0 = blockIdx.x * 32 + warp * 4;

    float acc[4][5];
#pragma unroll
    for (int r = 0; r < 4; r++)
#pragma unroll
        for (int j = 0; j < 5; j++) acc[r][j] = 0.0f;

    const float* fbase = feats + (size_t)row0 * Hd + lane * 4;

    float4 f[4], fn[4];
#pragma unroll
    for (int r = 0; r < 4; r++)
        f[r] = *reinterpret_cast<const float4*>(fbase + (size_t)r * Hd);

#pragma unroll
    for (int c = 0; c < 8; c++) {
        if (c < 7) {
#pragma unroll
            for (int r = 0; r < 4; r++)
                fn[r] = *reinterpret_cast<const float4*>(fbase + (size_t)r * Hd + (c + 1) * 128);
        }
        int k = c * 128 + lane * 4;
        float4 w[5];
#pragma unroll
        for (int j = 0; j < 5; j++)
            w[j] = *reinterpret_cast<const float4*>(&sWT[j * Hd + k]);

#pragma unroll
        for (int r = 0; r < 4; r++) {
#pragma unroll
            for (int j = 0; j < 5; j++) {
                float s = acc[r][j];
                s = fmaf(f[r].x, w[j].x, s);
                s = fmaf(f[r].y, w[j].y, s);
                s = fmaf(f[r].z, w[j].z, s);
                s = fmaf(f[r].w, w[j].w, s);
                acc[r][j] = s;
            }
        }
#pragma unroll
        for (int r = 0; r < 4; r++) f[r] = fn[r];
    }

#pragma unroll
    for (int r = 0; r < 4; r++) {
#pragma unroll
        for (int j = 0; j < 5; j++) {
            float v = acc[r][j];
            v += __shfl_xor_sync(0xffffffffu, v, 16);
            v += __shfl_xor_sync(0xffffffffu, v, 8);
            v += __shfl_xor_sync(0xffffffffu, v, 4);
            v += __shfl_xor_sync(0xffffffffu, v, 2);
            v += __shfl_xor_sync(0xffffffffu, v, 1);
            acc[r][j] = v;
        }
        if (lane < 5) {
            float e = acc[r][lane] + bias[lane];
            g_emis[(size_t)(row0 + r) * 8 + lane] = fmaxf(e, 0.0f);
        }
    }
}

// ---------------------------------------------------------------------------
// Kernel 2 v3: one block (512 thr) per batch.
//   warp 0      : sequential Viterbi — branchless SEL argmax, no lane guards,
//                 unrolled; stores bp to stride-32 table (all lanes STS)
//   warp 1      : numerator, then (bar 1) forward serial combine
//   warps 8-15  : forward partition fn, 8 chunked 5x5 prob-domain products
//   all 16 warps: chunked-exact parallel backtrack
//   last block  : reduces g_diff -> out[0]
// ---------------------------------------------------------------------------
__global__ __launch_bounds__(512) void k_scan(const int* __restrict__ labels,
                                              const float* __restrict__ start_t,
                                              const float* __restrict__ end_t,
                                              const float* __restrict__ trans,
                                              const float* __restrict__ weights,
                                              float* __restrict__ out) {
    __shared__ float sh_e[Sn * 8];            // 16 KB emissions
    __shared__ float sh_x[Sn * 8];            // 16 KB exp(emissions)
    __shared__ unsigned char sh_bp[Sn * 32];  // 16 KB bp, stride 32 (no guards)
    __shared__ unsigned char sh_cand[16 * 5 * 32];
    __shared__ unsigned char sh_map[16 * 8];
    __shared__ int sh_exit[16];
    __shared__ float sh_fwdM[8][25];
    __shared__ float sh_fwdS[8];
    __shared__ float sh_num, sh_logz;
    __shared__ int sh_last;
    __shared__ int sh_is_last_blk;

    const int b = blockIdx.x;
    const int tid = threadIdx.x;
    const int warp = tid >> 5;
    const int lane = tid & 31;

    // ---- stage emissions + exp(emissions) into shared ----
    {
        const float4* src = reinterpret_cast<const float4*>(g_emis + (size_t)b * Sn * 8);
        float4* de = reinterpret_cast<float4*>(sh_e);
        float4* dx = reinterpret_cast<float4*>(sh_x);
        for (int i = tid; i < Sn * 2; i += 512) {
            float4 v = src[i];
            de[i] = v;
            float4 xv;
            xv.x = __expf(v.x); xv.y = __expf(v.y);
            xv.z = __expf(v.z); xv.w = __expf(v.w);
            dx[i] = xv;
        }
    }
    __syncthreads();

    if (warp == 0) {
        // ================= sequential Viterbi (exact, branchless) =========
        const int jj = (lane < 5) ? lane : 0;
        const float T0 = trans[0 * Ln + jj];
        const float T1 = trans[1 * Ln + jj];
        const float T2 = trans[2 * Ln + jj];
        const float T3 = trans[3 * Ln + jj];
        const float T4 = trans[4 * Ln + jj];

        float v = start_t[jj] + sh_e[0 * 8 + jj];
        const float* ep = sh_e + 8 + jj;
        unsigned char* bp = sh_bp + 32 + lane;

#pragma unroll 4
        for (int t = 1; t < Sn; t++) {
            float e = *ep; ep += 8;

            float a0 = __shfl_sync(0xffffffffu, v, 0);
            float a1 = __shfl_sync(0xffffffffu, v, 1);
            float a2 = __shfl_sync(0xffffffffu, v, 2);
            float a3 = __shfl_sync(0xffffffffu, v, 3);
            float a4 = __shfl_sync(0xffffffffu, v, 4);

            float s0 = a0 + T0, s1 = a1 + T1, s2 = a2 + T2, s3 = a3 + T3, s4 = a4 + T4;
            // max tree on critical path; index via strict-> SELs (first-index ties,
            // identical to jnp.argmax), pure FSETP+SEL — no branches possible
            float m01 = fmaxf(s0, s1);  int b01 = (s1 > s0) ? 1 : 0;
            float m23 = fmaxf(s2, s3);  int b23 = (s3 > s2) ? 3 : 2;
            float m03 = fmaxf(m01, m23); int b03 = (m23 > m01) ? b23 : b01;
            float best = fmaxf(m03, s4); int bi  = (s4 > m03) ? 4 : b03;
            *bp = (unsigned char)bi; bp += 32;   // all 32 lanes store, no guard
            v = best + e;
        }

        float score = v + end_t[jj];
        float s0 = __shfl_sync(0xffffffffu, score, 0);
        float s1 = __shfl_sync(0xffffffffu, score, 1);
        float s2 = __shfl_sync(0xffffffffu, score, 2);
        float s3 = __shfl_sync(0xffffffffu, score, 3);
        float s4 = __shfl_sync(0xffffffffu, score, 4);
        if (lane == 0) {
            float m01 = fmaxf(s0, s1);  int b01 = (s1 > s0) ? 1 : 0;
            float m23 = fmaxf(s2, s3);  int b23 = (s3 > s2) ? 3 : 2;
            float m03 = fmaxf(m01, m23); int b03 = (m23 > m01) ? b23 : b01;
            sh_last = (s4 > m03) ? 4 : b03;
        }
    } else if (warp == 1) {
        // ================= numerator =================
        const int* lab = labels + b * Sn;
        float acc = 0.0f;
        for (int t = lane; t < Sn; t += 32) {
            int l = lab[t];
            acc = fmaf(weights[l], sh_e[t * 8 + l], acc);
            if (t > 0) acc += trans[lab[t - 1] * Ln + l];
        }
#pragma unroll
        for (int o = 16; o; o >>= 1) acc += __shfl_xor_sync(0xffffffffu, acc, o);
        if (lane == 0) {
            acc += start_t[lab[0]] + end_t[lab[Sn - 1]];
            sh_num = acc;
        }
        asm volatile("bar.sync 1, 288;" ::: "memory");
        // ---- serial combine of 8 chunk matrices -> logZ ----
        if (lane == 0) {
            float a0 = __expf(start_t[0] + sh_e[0]);
            float a1 = __expf(start_t[1] + sh_e[1]);
            float a2 = __expf(start_t[2] + sh_e[2]);
            float a3 = __expf(start_t[3] + sh_e[3]);
            float a4 = __expf(start_t[4] + sh_e[4]);
            float ls = 0.0f;
#pragma unroll
            for (int c = 0; c < 8; c++) {
                const float* M = sh_fwdM[c];
                float n0 = a0*M[0] + a1*M[5] + a2*M[10] + a3*M[15] + a4*M[20];
                float n1 = a0*M[1] + a1*M[6] + a2*M[11] + a3*M[16] + a4*M[21];
                float n2 = a0*M[2] + a1*M[7] + a2*M[12] + a3*M[17] + a4*M[22];
                float n3 = a0*M[3] + a1*M[8] + a2*M[13] + a3*M[18] + a4*M[23];
                float n4 = a0*M[4] + a1*M[9] + a2*M[14] + a3*M[19] + a4*M[24];
                float m = fmaxf(fmaxf(fmaxf(n0, n1), fmaxf(n2, n3)), n4);
                float inv = __fdividef(1.0f, m);
                a0 = n0 * inv; a1 = n1 * inv; a2 = n2 * inv; a3 = n3 * inv; a4 = n4 * inv;
                ls += __logf(m) + sh_fwdS[c];
            }
            float z = a0 * __expf(end_t[0]) + a1 * __expf(end_t[1])
                    + a2 * __expf(end_t[2]) + a3 * __expf(end_t[3])
                    + a4 * __expf(end_t[4]);
            sh_logz = __logf(z) + ls;
        }
    } else if (warp >= 8) {
        // ================= forward: chunked 5x5 matrix products ============
        const int fc = warp - 8;
        const int i = (lane < 25) ? (lane / 5) : 0;
        const int j = lane % 5;
        float eT0 = __expf(trans[0 * Ln + j]);
        float eT1 = __expf(trans[1 * Ln + j]);
        float eT2 = __expf(trans[2 * Ln + j]);
        float eT3 = __expf(trans[3 * Ln + j]);
        float eT4 = __expf(trans[4 * Ln + j]);

        float m = (i == j) ? 1.0f : 0.0f;
        float lsc = 0.0f;
        const int t0 = (fc == 0) ? 1 : 64 * fc;
        const int t1 = 64 * fc + 63;
        int cnt = 0;
        const int base = i * 5;
        for (int t = t0; t <= t1; t++) {
            float x = sh_x[t * 8 + j];
            float r0 = __shfl_sync(0xffffffffu, m, base + 0);
            float r1 = __shfl_sync(0xffffffffu, m, base + 1);
            float r2 = __shfl_sync(0xffffffffu, m, base + 2);
            float r3 = __shfl_sync(0xffffffffu, m, base + 3);
            float r4 = __shfl_sync(0xffffffffu, m, base + 4);
            float s = r0 * eT0;
            s = fmaf(r1, eT1, s);
            s = fmaf(r2, eT2, s);
            s = fmaf(r3, eT3, s);
            s = fmaf(r4, eT4, s);
            m = s * x;
            if ((++cnt & 7) == 0) {
                float mm = (lane < 25) ? m : 0.0f;
#pragma unroll
                for (int o = 16; o; o >>= 1)
                    mm = fmaxf(mm, __shfl_xor_sync(0xffffffffu, mm, o));
                m = __fdividef(m, mm);
                lsc += __logf(mm);
            }
        }
        if (lane < 25) sh_fwdM[fc][lane] = m;
        if (lane == 0) sh_fwdS[fc] = lsc;
        asm volatile("bar.sync 1, 288;" ::: "memory");
    }

    __syncthreads();  // bp + sh_last + sh_num + sh_logz ready

    if (tid == 0) {
        g_diff[b] = sh_num - sh_logz;
        __threadfence();
        unsigned int old = atomicAdd(&g_cnt, 1u);
        sh_is_last_blk = (old == Bn - 1);
    }

    // ================= chunked-exact parallel backtrack =================
    {
        const int c = warp;
        if (lane < 5) {
            int tag = lane;
            const int tstart = (c == 0) ? 1 : 32 * c;
            for (int t = 32 * c + 31; t >= tstart; t--) {
                sh_cand[(c * 5 + lane) * 32 + (t - 32 * c)] = (unsigned char)tag;
                tag = sh_bp[t * 32 + tag];
            }
            if (c == 0) sh_cand[lane * 32 + 0] = (unsigned char)tag;
            sh_map[c * 8 + lane] = (unsigned char)tag;
        }
    }
    __syncthreads();

    if (tid == 0) {
        int tg = sh_last;
        sh_exit[15] = tg;
        for (int c = 15; c >= 1; c--) {
            tg = sh_map[c * 8 + tg];
            sh_exit[c - 1] = tg;
        }
    }
    __syncthreads();

    {
        const int c = warp;
        const int ex = sh_exit[c];
        out[1 + (size_t)b * Sn + c * 32 + lane] =
            (float)sh_cand[(c * 5 + ex) * 32 + lane];
    }

    __syncthreads();
    // ---- merged k_final: last block reduces g_diff -> loss ----
    if (sh_is_last_blk && warp == 0) {
        __threadfence();
        float acc = __ldcg(&g_diff[lane]) + __ldcg(&g_diff[lane + 32]);
#pragma unroll
        for (int o = 16; o; o >>= 1) acc += __shfl_xor_sync(0xffffffffu, acc, o);
        if (lane == 0) {
            out[0] = -acc * (1.0f / (float)(Bn * Sn));
            g_cnt = 0;  // reset for next graph replay
        }
    }
}

extern "C" void kernel_launch(void* const* d_in, const int* in_sizes, int n_in,
                              void* d_out, int out_size) {
    const float* feats   = (const float*)d_in[0];
    const int*   labels  = (const int*)  d_in[1];
    // d_in[2] = mask (all ones; reference requires mask[:,0] on)
    const float* W       = (const float*)d_in[3];
    const float* bias    = (const float*)d_in[4];
    const float* start_t = (const float*)d_in[5];
    const float* end_t   = (const float*)d_in[6];
    const float* trans   = (const float*)d_in[7];
    const float* weights = (const float*)d_in[8];
    float* out = (float*)d_out;

    k_emis<<<1024, 256>>>(feats, W, bias);
    k_scan<<<Bn, 512>>>(labels, start_t, end_t, trans, weights, out);
}

// round 8
// speedup vs baseline: 1.4404x; 1.0267x over previous
#include <cuda_runtime.h>
#include <cstdint>

#define Sn 512
#define Bn 64
#define Hd 1024
#define Ln 5

// scratch: emissions padded to stride 8; per-batch loss terms; block counter
__device__ float g_emis[(size_t)Bn * Sn * 8];
__device__ float g_diff[Bn];
__device__ unsigned int g_cnt;

// ---------------------------------------------------------------------------
// Kernel 1 v5: emissions = relu(feats @ W + b)
// 2 rows/warp (low regs) -> 4 CTAs/SM (32 warps of MLP); __ldcs streaming
// loads; double-buffered register prefetch. grid 2048 x 256.
// ---------------------------------------------------------------------------
__global__ __launch_bounds__(256, 4) void k_emis(const float* __restrict__ feats,
                                                 const float* __restrict__ W,
                                                 const float* __restrict__ bias) {
    __shared__ float sWT[Ln * Hd];  // transposed: sWT[j*Hd + k] = W[k*Ln + j]
    int tid = threadIdx.x;
    for (int i = tid; i < Ln * Hd; i += 256) {
        int j = i >> 10;
        int k = i & (Hd - 1);
        sWT[i] = W[k * Ln + j];
    }
    __syncthreads();

    int warp = tid >> 5, lane = tid & 31;
    int row0 = blockIdx.x * 16 + warp * 2;

    float acc[2][5];
#pragma unroll
    for (int r = 0; r < 2; r++)
#pragma unroll
        for (int j = 0; j < 5; j++) acc[r][j] = 0.0f;

    const float* fbase = feats + (size_t)row0 * Hd + lane * 4;

    float4 f[2], fn[2];
#pragma unroll
    for (int r = 0; r < 2; r++)
        f[r] = __ldcs(reinterpret_cast<const float4*>(fbase + (size_t)r * Hd));

#pragma unroll
    for (int c = 0; c < 8; c++) {
        if (c < 7) {
#pragma unroll
            for (int r = 0; r < 2; r++)
                fn[r] = __ldcs(reinterpret_cast<const float4*>(
                    fbase + (size_t)r * Hd + (c + 1) * 128));
        }
        int k = c * 128 + lane * 4;
        float4 w[5];
#pragma unroll
        for (int j = 0; j < 5; j++)
            w[j] = *reinterpret_cast<const float4*>(&sWT[j * Hd + k]);

#pragma unroll
        for (int r = 0; r < 2; r++) {
#pragma unroll
            for (int j = 0; j < 5; j++) {
                float s = acc[r][j];
                s = fmaf(f[r].x, w[j].x, s);
                s = fmaf(f[r].y, w[j].y, s);
                s = fmaf(f[r].z, w[j].z, s);
                s = fmaf(f[r].w, w[j].w, s);
                acc[r][j] = s;
            }
        }
#pragma unroll
        for (int r = 0; r < 2; r++) f[r] = fn[r];
    }

#pragma unroll
    for (int r = 0; r < 2; r++) {
#pragma unroll
        for (int j = 0; j < 5; j++) {
            float v = acc[r][j];
            v += __shfl_xor_sync(0xffffffffu, v, 16);
            v += __shfl_xor_sync(0xffffffffu, v, 8);
            v += __shfl_xor_sync(0xffffffffu, v, 4);
            v += __shfl_xor_sync(0xffffffffu, v, 2);
            v += __shfl_xor_sync(0xffffffffu, v, 1);
            acc[r][j] = v;
        }
        if (lane < 5) {
            float e = acc[r][lane] + bias[lane];
            g_emis[(size_t)(row0 + r) * 8 + lane] = fmaxf(e, 0.0f);
        }
    }
}

// ---------------------------------------------------------------------------
// Kernel 2 v4: one block (512 thr) per batch.
//   warp 0      : sequential Viterbi, deferred-bp: hot loop stores alpha(t)
//                 vectors only (no argmax SELs on the serial path)
//   warp 1      : numerator, then (bar 1) forward serial combine
//   warps 8-15  : forward partition fn, 8 chunked 5x5 prob-domain products
//   all 16 warps: chunked-exact parallel backtrack, bp recomputed from
//                 stored alphas (bit-identical argmax, first-index ties)
//   last block  : reduces g_diff -> out[0]
// ---------------------------------------------------------------------------
__global__ __launch_bounds__(512) void k_scan(const int* __restrict__ labels,
                                              const float* __restrict__ start_t,
                                              const float* __restrict__ end_t,
                                              const float* __restrict__ trans,
                                              const float* __restrict__ weights,
                                              float* __restrict__ out) {
    __shared__ float sh_e[Sn * 8];            // 16 KB emissions
    __shared__ float sh_x[Sn * 8];            // 16 KB exp(emissions)
    __shared__ float sh_al[Sn * 8];           // 16 KB Viterbi alpha vectors
    __shared__ float sh_tr[25];               // trans copy for backtrack
    __shared__ unsigned char sh_cand[16 * 5 * 32];
    __shared__ unsigned char sh_map[16 * 8];
    __shared__ int sh_exit[16];
    __shared__ float sh_fwdM[8][25];
    __shared__ float sh_fwdS[8];
    __shared__ float sh_num, sh_logz;
    __shared__ int sh_last;
    __shared__ int sh_is_last_blk;

    const int b = blockIdx.x;
    const int tid = threadIdx.x;
    const int warp = tid >> 5;
    const int lane = tid & 31;

    // ---- stage emissions + exp(emissions) into shared ----
    {
        const float4* src = reinterpret_cast<const float4*>(g_emis + (size_t)b * Sn * 8);
        float4* de = reinterpret_cast<float4*>(sh_e);
        float4* dx = reinterpret_cast<float4*>(sh_x);
        for (int i = tid; i < Sn * 2; i += 512) {
            float4 v = src[i];
            de[i] = v;
            float4 xv;
            xv.x = __expf(v.x); xv.y = __expf(v.y);
            xv.z = __expf(v.z); xv.w = __expf(v.w);
            dx[i] = xv;
        }
        if (tid < 25) sh_tr[tid] = trans[tid];
    }
    __syncthreads();

    if (warp == 0) {
        // ========== sequential Viterbi, deferred backpointers ==========
        const int jj = (lane < 5) ? lane : 0;
        const float T0 = trans[0 * Ln + jj];
        const float T1 = trans[1 * Ln + jj];
        const float T2 = trans[2 * Ln + jj];
        const float T3 = trans[3 * Ln + jj];
        const float T4 = trans[4 * Ln + jj];

        float v = start_t[jj] + sh_e[0 * 8 + jj];
        sh_al[0 * 8 + jj] = v;   // lanes>=5 mirror lane 0 (same value, same addr)
        const float* ep = sh_e + 8 + jj;
        float* ap = sh_al + 8 + jj;

#pragma unroll 4
        for (int t = 1; t < Sn; t++) {
            float e = *ep; ep += 8;

            float a0 = __shfl_sync(0xffffffffu, v, 0);
            float a1 = __shfl_sync(0xffffffffu, v, 1);
            float a2 = __shfl_sync(0xffffffffu, v, 2);
            float a3 = __shfl_sync(0xffffffffu, v, 3);
            float a4 = __shfl_sync(0xffffffffu, v, 4);

            float s0 = a0 + T0, s1 = a1 + T1, s2 = a2 + T2, s3 = a3 + T3, s4 = a4 + T4;
            float m01 = fmaxf(s0, s1), m23 = fmaxf(s2, s3);
            float best = fmaxf(fmaxf(m01, m23), s4);
            v = best + e;
            *ap = v; ap += 8;     // store alpha(t); no argmax here
        }

        float score = v + end_t[jj];
        float s0 = __shfl_sync(0xffffffffu, score, 0);
        float s1 = __shfl_sync(0xffffffffu, score, 1);
        float s2 = __shfl_sync(0xffffffffu, score, 2);
        float s3 = __shfl_sync(0xffffffffu, score, 3);
        float s4 = __shfl_sync(0xffffffffu, score, 4);
        if (lane == 0) {
            float m01 = fmaxf(s0, s1);  int b01 = (s1 > s0) ? 1 : 0;
            float m23 = fmaxf(s2, s3);  int b23 = (s3 > s2) ? 3 : 2;
            float m03 = fmaxf(m01, m23); int b03 = (m23 > m01) ? b23 : b01;
            sh_last = (s4 > m03) ? 4 : b03;
        }
    } else if (warp == 1) {
        // ================= numerator =================
        const int* lab = labels + b * Sn;
        float acc = 0.0f;
        for (int t = lane; t < Sn; t += 32) {
            int l = lab[t];
            acc = fmaf(weights[l], sh_e[t * 8 + l], acc);
            if (t > 0) acc += trans[lab[t - 1] * Ln + l];
        }
#pragma unroll
        for (int o = 16; o; o >>= 1) acc += __shfl_xor_sync(0xffffffffu, acc, o);
        if (lane == 0) {
            acc += start_t[lab[0]] + end_t[lab[Sn - 1]];
            sh_num = acc;
        }
        asm volatile("bar.sync 1, 288;" ::: "memory");
        // ---- serial combine of 8 chunk matrices -> logZ ----
        if (lane == 0) {
            float a0 = __expf(start_t[0] + sh_e[0]);
            float a1 = __expf(start_t[1] + sh_e[1]);
            float a2 = __expf(start_t[2] + sh_e[2]);
            float a3 = __expf(start_t[3] + sh_e[3]);
            float a4 = __expf(start_t[4] + sh_e[4]);
            float ls = 0.0f;
#pragma unroll
            for (int c = 0; c < 8; c++) {
                const float* M = sh_fwdM[c];
                float n0 = a0*M[0] + a1*M[5] + a2*M[10] + a3*M[15] + a4*M[20];
                float n1 = a0*M[1] + a1*M[6] + a2*M[11] + a3*M[16] + a4*M[21];
                float n2 = a0*M[2] + a1*M[7] + a2*M[12] + a3*M[17] + a4*M[22];
                float n3 = a0*M[3] + a1*M[8] + a2*M[13] + a3*M[18] + a4*M[23];
                float n4 = a0*M[4] + a1*M[9] + a2*M[14] + a3*M[19] + a4*M[24];
                float m = fmaxf(fmaxf(fmaxf(n0, n1), fmaxf(n2, n3)), n4);
                float inv = __fdividef(1.0f, m);
                a0 = n0 * inv; a1 = n1 * inv; a2 = n2 * inv; a3 = n3 * inv; a4 = n4 * inv;
                ls += __logf(m) + sh_fwdS[c];
            }
            float z = a0 * __expf(end_t[0]) + a1 * __expf(end_t[1])
                    + a2 * __expf(end_t[2]) + a3 * __expf(end_t[3])
                    + a4 * __expf(end_t[4]);
            sh_logz = __logf(z) + ls;
        }
    } else if (warp >= 8) {
        // ================= forward: chunked 5x5 matrix products ============
        const int fc = warp - 8;
        const int i = (lane < 25) ? (lane / 5) : 0;
        const int j = lane % 5;
        float eT0 = __expf(trans[0 * Ln + j]);
        float eT1 = __expf(trans[1 * Ln + j]);
        float eT2 = __expf(trans[2 * Ln + j]);
        float eT3 = __expf(trans[3 * Ln + j]);
        float eT4 = __expf(trans[4 * Ln + j]);

        float m = (i == j) ? 1.0f : 0.0f;
        float lsc = 0.0f;
        const int t0 = (fc == 0) ? 1 : 64 * fc;
        const int t1 = 64 * fc + 63;
        int cnt = 0;
        const int base = i * 5;
        for (int t = t0; t <= t1; t++) {
            float x = sh_x[t * 8 + j];
            float r0 = __shfl_sync(0xffffffffu, m, base + 0);
            float r1 = __shfl_sync(0xffffffffu, m, base + 1);
            float r2 = __shfl_sync(0xffffffffu, m, base + 2);
            float r3 = __shfl_sync(0xffffffffu, m, base + 3);
            float r4 = __shfl_sync(0xffffffffu, m, base + 4);
            float s = r0 * eT0;
            s = fmaf(r1, eT1, s);
            s = fmaf(r2, eT2, s);
            s = fmaf(r3, eT3, s);
            s = fmaf(r4, eT4, s);
            m = s * x;
            if ((++cnt & 7) == 0) {
                float mm = (lane < 25) ? m : 0.0f;
#pragma unroll
                for (int o = 16; o; o >>= 1)
                    mm = fmaxf(mm, __shfl_xor_sync(0xffffffffu, mm, o));
                m = __fdividef(m, mm);
                lsc += __logf(mm);
            }
        }
        if (lane < 25) sh_fwdM[fc][lane] = m;
        if (lane == 0) sh_fwdS[fc] = lsc;
        asm volatile("bar.sync 1, 288;" ::: "memory");
    }

    __syncthreads();  // alphas + sh_last + sh_num + sh_logz ready

    if (tid == 0) {
        g_diff[b] = sh_num - sh_logz;
        __threadfence();
        unsigned int old = atomicAdd(&g_cnt, 1u);
        sh_is_last_blk = (old == Bn - 1);
    }

    // ===== chunked-exact parallel backtrack, bp recomputed from alphas =====
    {
        const int c = warp;
        if (lane < 5) {
            int tag = lane;
            const int tstart = (c == 0) ? 1 : 32 * c;
            for (int t = 32 * c + 31; t >= tstart; t--) {
                sh_cand[(c * 5 + lane) * 32 + (t - 32 * c)] = (unsigned char)tag;
                // bp(t, tag) = argmax_i alpha_i(t-1) + T[i][tag]  (first-index ties)
                const float* al = sh_al + (t - 1) * 8;
                float s0 = al[0] + sh_tr[0 * Ln + tag];
                float s1 = al[1] + sh_tr[1 * Ln + tag];
                float s2 = al[2] + sh_tr[2 * Ln + tag];
                float s3 = al[3] + sh_tr[3 * Ln + tag];
                float s4 = al[4] + sh_tr[4 * Ln + tag];
                float m01 = fmaxf(s0, s1);  int b01 = (s1 > s0) ? 1 : 0;
                float m23 = fmaxf(s2, s3);  int b23 = (s3 > s2) ? 3 : 2;
                float m03 = fmaxf(m01, m23); int b03 = (m23 > m01) ? b23 : b01;
                tag = (s4 > m03) ? 4 : b03;
            }
            if (c == 0) sh_cand[lane * 32 + 0] = (unsigned char)tag;
            sh_map[c * 8 + lane] = (unsigned char)tag;
        }
    }
    __syncthreads();

    if (tid == 0) {
        int tg = sh_last;
        sh_exit[15] = tg;
        for (int c = 15; c >= 1; c--) {
            tg = sh_map[c * 8 + tg];
            sh_exit[c - 1] = tg;
        }
    }
    __syncthreads();

    {
        const int c = warp;
        const int ex = sh_exit[c];
        out[1 + (size_t)b * Sn + c * 32 + lane] =
            (float)sh_cand[(c * 5 + ex) * 32 + lane];
    }

    __syncthreads();
    // ---- merged k_final: last block reduces g_diff -> loss ----
    if (sh_is_last_blk && warp == 0) {
        __threadfence();
        float acc = __ldcg(&g_diff[lane]) + __ldcg(&g_diff[lane + 32]);
#pragma unroll
        for (int o = 16; o; o >>= 1) acc += __shfl_xor_sync(0xffffffffu, acc, o);
        if (lane == 0) {
            out[0] = -acc * (1.0f / (float)(Bn * Sn));
            g_cnt = 0;  // reset for next graph replay
        }
    }
}

extern "C" void kernel_launch(void* const* d_in, const int* in_sizes, int n_in,
                              void* d_out, int out_size) {
    const float* feats   = (const float*)d_in[0];
    const int*   labels  = (const int*)  d_in[1];
    // d_in[2] = mask (all ones; reference requires mask[:,0] on)
    const float* W       = (const float*)d_in[3];
    const float* bias    = (const float*)d_in[4];
    const float* start_t = (const float*)d_in[5];
    const float* end_t   = (const float*)d_in[6];
    const float* trans   = (const float*)d_in[7];
    const float* weights = (const float*)d_in[8];
    float* out = (float*)d_out;

    k_emis<<<2048, 256>>>(feats, W, bias);
    k_scan<<<Bn, 512>>>(labels, start_t, end_t, trans, weights, out);
}